// round 16
// baseline (speedup 1.0000x reference)
#include <cuda_runtime.h>
#include <cuda_bf16.h>
#include <cstdint>

#define BB 16
#define NN 8192
#define HH 128
#define GG 10
#define DCC 16
#define NBLK 6
#define K1 154          // H + G + DC (global-path cat width)
#define KPROJ0 272
#define KBLK 282
#define NP 64           // points per local CTA
#define NTL 128         // local tiles per batch
#define NPART 256       // pooling partial columns per batch (2 per tile)
#define NT0 32          // proj tiles per batch

// ---- k_local SMEM (2 CTAs/SM): one A region (reused W1->W2), one B region
// (reused cat->h). bf16 tiles, stride 272B (17x16B, conflict-free).
#define SAB 272
#define TILE_B (HH * SAB)       // 34816 (A plane: 128 rows)
#define TILE_S (NP * SAB)       // 17408 (B plane: 64 rows)
#define O_AH 0                  // W1 hi, then W2 hi
#define O_AL (TILE_B)           // W1 lo, then W2 lo
#define O_BH (2 * TILE_B)       // cat hi, then h hi
#define O_BL (2 * TILE_B + TILE_S)
#define O_STG 0                 // fp32 staging [64][132] (last block, after GEMM2)
#define O_MB  (2 * TILE_B + 2 * TILE_S)   // 104448
#define O_B1V (O_MB)
#define O_B2V (O_MB + 512)
#define O_MK  (O_MB + 1024)
#define O_OW  (O_MB + 1280)
#define O_OB  (O_MB + 2816)
#define SMEM_SZ (O_MB + 2848)   // 107296 bytes -> 2 CTAs/SM

typedef unsigned int u32;

// persistent scratch (allocation-free rule: __device__ globals)
__device__ float g_xl[(size_t)BB * HH * NN];      // (B, H, N)
__device__ float g_part[BB * NPART * HH];
__device__ float g_part0[BB * NT0 * HH];
__device__ float g_cnt0[BB * NT0];
__device__ float g_cnt[BB];
__device__ float g_xg[BB * GG];
__device__ float g_hb[BB * HH];                   // folded W1[:,128:154]@[xg;ctx]
// pre-split bf16 weight planes, ALREADY in padded smem layout (272B rows).
__device__ char  g_wsp[(size_t)NBLK * 4 * TILE_B];

__device__ __forceinline__ float lrelu(float v) { return fmaxf(v, 0.01f * v); }

__device__ __forceinline__ u32 s2u(const void* p) {
    u32 a;
    asm("{ .reg .u64 t; cvta.to.shared.u64 t, %1; cvt.u32.u64 %0, t; }" : "=r"(a) : "l"(p));
    return a;
}
__device__ __forceinline__ void bsplit(float v, __nv_bfloat16& h, __nv_bfloat16& l) {
    h = __float2bfloat16(v);
    l = __float2bfloat16(v - __bfloat162float(h));
}

#define LDM4(r, addr) \
    asm volatile("ldmatrix.sync.aligned.m8n8.x4.shared.b16 {%0,%1,%2,%3}, [%4];" \
        : "=r"((r)[0]), "=r"((r)[1]), "=r"((r)[2]), "=r"((r)[3]) : "r"(addr))

#define MMA(c, a, b0_, b1_) \
    asm volatile("mma.sync.aligned.m16n8k16.row.col.f32.bf16.bf16.f32 " \
        "{%0,%1,%2,%3}, {%4,%5,%6,%7}, {%8,%9}, {%0,%1,%2,%3};" \
        : "+f"((c)[0]), "+f"((c)[1]), "+f"((c)[2]), "+f"((c)[3]) \
        : "r"((a)[0]), "r"((a)[1]), "r"((a)[2]), "r"((a)[3]), "r"(b0_), "r"(b1_))

// D[32 x 32 per warp] += (2-term split) A[m,k] x B[n,k]^T over K=128.
// Per k-step: 8 LDM4 -> 24 MMAs over 8 accumulator quads.
__device__ __forceinline__ void gemm32(u32 aH, u32 aL, u32 bH, u32 bL,
                                       int lane, int m_base, int n_base, float* acc)
{
    u32 a0 = aH + (u32)(m_base + (lane & 15)) * SAB + ((lane & 16) ? 16u : 0u);
    u32 dA = aL - aH;
    u32 bRow = (u32)((lane & 7) + ((lane & 16) >> 1));
    u32 b0 = bH + ((u32)n_base + bRow) * SAB + ((lane & 8) ? 16u : 0u);
    u32 dB = bL - bH;
    #pragma unroll 2
    for (int ks = 0; ks < 8; ++ks) {
        u32 ak = (u32)ks * 32u;
        u32 ah[2][4], al[2][4], bh[2][4], bl[2][4];
        LDM4(ah[0], a0 + ak);
        LDM4(ah[1], a0 + 16u * SAB + ak);
        LDM4(bh[0], b0 + ak);
        LDM4(bh[1], b0 + 16u * SAB + ak);
        LDM4(al[0], a0 + dA + ak);
        LDM4(al[1], a0 + dA + 16u * SAB + ak);
        LDM4(bl[0], b0 + dB + ak);
        LDM4(bl[1], b0 + dB + 16u * SAB + ak);
        #pragma unroll
        for (int mi = 0; mi < 2; ++mi)
            #pragma unroll
            for (int nq = 0; nq < 4; ++nq)
                MMA(acc + (mi * 4 + nq) * 4, ah[mi],
                    bh[nq >> 1][(nq & 1) * 2], bh[nq >> 1][(nq & 1) * 2 + 1]);
        #pragma unroll
        for (int mi = 0; mi < 2; ++mi)
            #pragma unroll
            for (int nq = 0; nq < 4; ++nq)
                MMA(acc + (mi * 4 + nq) * 4, ah[mi],
                    bl[nq >> 1][(nq & 1) * 2], bl[nq >> 1][(nq & 1) * 2 + 1]);
        #pragma unroll
        for (int mi = 0; mi < 2; ++mi)
            #pragma unroll
            for (int nq = 0; nq < 4; ++nq)
                MMA(acc + (mi * 4 + nq) * 4, al[mi],
                    bh[nq >> 1][(nq & 1) * 2], bh[nq >> 1][(nq & 1) * 2 + 1]);
    }
}

// ---------------------------------------------------------------------------
// k_prep: split W1[:, :128] and W2 into bf16 hi/lo planes in the padded
// smem layout. grid (NBLK, 2), 128 threads (thread = output row).
// ---------------------------------------------------------------------------
__global__ __launch_bounds__(128) void k_prep(const float* __restrict__ l1w,
                                              const float* __restrict__ l2w)
{
    int blk = blockIdx.x, mat = blockIdx.y, m = threadIdx.x;
    const float* row = (mat == 0) ? (l1w + ((size_t)blk * HH + m) * K1)
                                  : (l2w + ((size_t)blk * HH + m) * HH);
    char* hp = g_wsp + (size_t)blk * 4 * TILE_B + (size_t)(mat * 2 + 0) * TILE_B + (size_t)m * SAB;
    char* lp = g_wsp + (size_t)blk * 4 * TILE_B + (size_t)(mat * 2 + 1) * TILE_B + (size_t)m * SAB;
    for (int k = 0; k < HH; ++k) {
        __nv_bfloat16 h, l; bsplit(row[k], h, l);
        *(__nv_bfloat16*)(hp + 2 * k) = h;
        *(__nv_bfloat16*)(lp + 2 * k) = l;
    }
}

// ---------------------------------------------------------------------------
// k_proj: unchanged.
// ---------------------------------------------------------------------------
__global__ __launch_bounds__(256) void k_proj(
    const float* __restrict__ x, const float* __restrict__ mask,
    const float* __restrict__ lw, const float* __restrict__ lb)
{
    __shared__ float sw[HH * 3], sbv[HH], st[32][257], sp[HH], sc[8];
    int b = blockIdx.x, tile = blockIdx.y, tid = threadIdx.x;
    int wid = tid >> 5, lid = tid & 31;
    int p0 = tile * 256, p = p0 + tid;
    for (int i = tid; i < HH * 3; i += 256) sw[i] = lw[i];
    for (int i = tid; i < HH; i += 256) { sbv[i] = lb[i]; sp[i] = 0.f; }
    __syncthreads();
    const float* xr = x + ((size_t)b * NN + p) * 3;
    float x0 = xr[0], x1 = xr[1], x2 = xr[2];
    float m = mask[(size_t)b * NN + p];
    float cacc = m;
    #pragma unroll
    for (int o = 16; o; o >>= 1) cacc += __shfl_xor_sync(0xffffffffu, cacc, o);
    if (lid == 0) sc[wid] = cacc;

    for (int hc = 0; hc < 4; ++hc) {
        #pragma unroll
        for (int r = 0; r < 32; ++r) {
            int h = hc * 32 + r;
            float v = fmaf(x0, sw[h * 3], fmaf(x1, sw[h * 3 + 1], fmaf(x2, sw[h * 3 + 2], sbv[h])));
            st[r][tid] = lrelu(v) * m;
        }
        __syncthreads();
        for (int idx = tid; idx < 32 * 256; idx += 256) {
            int r = idx >> 8, q = idx & 255;
            g_xl[(size_t)b * HH * NN + (size_t)(hc * 32 + r) * NN + p0 + q] = st[r][q];
        }
        #pragma unroll
        for (int rr = 0; rr < 4; ++rr) {
            int r = wid * 4 + rr;
            float a = 0.f;
            #pragma unroll
            for (int q = 0; q < 8; ++q) a += st[r][lid + q * 32];
            #pragma unroll
            for (int o = 16; o; o >>= 1) a += __shfl_xor_sync(0xffffffffu, a, o);
            if (lid == 0) sp[hc * 32 + r] += a;
        }
        __syncthreads();
    }
    if (tid < HH) g_part0[(b * NT0 + tile) * HH + tid] = sp[tid];
    if (tid == 0) {
        float c = 0.f;
        #pragma unroll
        for (int i = 0; i < 8; ++i) c += sc[i];
        g_cnt0[b * NT0 + tile] = c;
    }
}

// ---------------------------------------------------------------------------
// k_global: 1024 threads / 32 warps (unchanged from R15).
// ---------------------------------------------------------------------------
__device__ __forceinline__ float dotw(const float* __restrict__ w,
                                      const float* __restrict__ xs, int n, int lid) {
    float a = 0.f;
    for (int k = lid; k < n; k += 32) a = fmaf(w[k], xs[k], a);
    #pragma unroll
    for (int o = 16; o; o >>= 1) a += __shfl_xor_sync(0xffffffffu, a, o);
    return a;
}

__global__ __launch_bounds__(1024) void k_global(
    int phase, int blk, const float* __restrict__ ctx,
    const float* __restrict__ pg0w, const float* __restrict__ pg0b,
    const float* __restrict__ pg1w, const float* __restrict__ pg1b,
    const float* __restrict__ pg2w, const float* __restrict__ pg2b,
    const float* __restrict__ g1w, const float* __restrict__ g1b,
    const float* __restrict__ g2w, const float* __restrict__ g2b,
    const float* __restrict__ l1w)
{
    __shared__ float red[8][HH];
    __shared__ float sp[KBLK], spP[KPROJ0], sh[HH], sh2[HH], sxg[GG], sgc[GG + DCC];
    __shared__ float scn;
    int b = blockIdx.x, tid = threadIdx.x, wid = tid >> 5, lid = tid & 31;
    int j = tid & 127, grp = tid >> 7;   // 8 groups of 128

    float s = 0.f;
    if (phase == 0) {
        #pragma unroll
        for (int c = grp; c < NT0; c += 8) s += g_part0[(b * NT0 + c) * HH + j];
    } else {
        #pragma unroll 8
        for (int c = grp; c < NPART; c += 8) s += g_part[(b * NPART + c) * HH + j];
    }
    red[grp][j] = s;
    if (wid == 0) {
        float cc;
        if (phase == 0) {
            cc = g_cnt0[b * NT0 + lid];
            #pragma unroll
            for (int o = 16; o; o >>= 1) cc += __shfl_xor_sync(0xffffffffu, cc, o);
            if (lid == 0) { scn = cc; g_cnt[b] = cc; }
        } else if (lid == 0) scn = g_cnt[b];
    }
    __syncthreads();
    float cnt = scn;
    if (tid < HH) {
        float t = 0.f;
        #pragma unroll
        for (int g = 0; g < 8; ++g) t += red[g][tid];
        sp[tid] = t / cnt; sp[HH + tid] = t;
        if (phase == 0) { spP[tid] = t / cnt; spP[HH + tid] = t; }
    }
    if (tid < DCC) {
        float cv = ctx[b * DCC + tid];
        sp[2 * HH + GG + tid] = cv;
        sgc[GG + tid] = cv;
        if (phase == 0) spP[2 * HH + tid] = cv;
    }
    __syncthreads();

    if (phase == 0) {
        for (int o = wid; o < HH; o += 32) {
            float a = dotw(pg0w + (size_t)o * KPROJ0, spP, KPROJ0, lid);
            if (lid == 0) sh[o] = lrelu(a + pg0b[o]);
        }
        __syncthreads();
        for (int o = wid; o < HH; o += 32) {
            float a = dotw(pg1w + (size_t)o * HH, sh, HH, lid);
            if (lid == 0) sh2[o] = lrelu(a + pg1b[o]);
        }
        __syncthreads();
        if (wid < GG) {
            int o = wid;
            float a = dotw(pg2w + (size_t)o * HH, sh2, HH, lid);
            if (lid == 0) sxg[o] = lrelu(a + pg2b[o]);
        }
        __syncthreads();
    } else {
        if (tid < GG) sxg[tid] = g_xg[b * GG + tid];
        __syncthreads();
    }

    if (tid < GG) sp[2 * HH + tid] = sxg[tid];
    __syncthreads();
    for (int o = wid; o < HH; o += 32) {
        float a = dotw(g1w + ((size_t)blk * HH + o) * KBLK, sp, KBLK, lid);
        if (lid == 0) sh[o] = lrelu(a + g1b[blk * HH + o]);
    }
    __syncthreads();
    if (wid < GG) {
        int o = wid;
        float a = dotw(g2w + ((size_t)blk * GG + o) * HH, sh, HH, lid) + g2b[blk * GG + o];
        if (lid == 0) {
            float v = lrelu(a + sxg[o]);
            g_xg[b * GG + o] = v;
            sgc[o] = v;            // NEW xg for the folded bias
        }
    }
    __syncthreads();

    // folded bias: hb[m] = W1[m, 128:154] @ [xg_new; ctx]
    for (int o = wid; o < HH; o += 32) {
        const float* wrow = l1w + ((size_t)blk * HH + o) * K1 + HH;
        float a = 0.f;
        if (lid < GG + DCC) a = wrow[lid] * sgc[lid];
        #pragma unroll
        for (int of = 16; of; of >>= 1) a += __shfl_xor_sync(0xffffffffu, a, of);
        if (lid == 0) g_hb[b * HH + o] = a;
    }
}

// ---------------------------------------------------------------------------
// k_local: mma.sync bf16-split two-layer MLP. grid (128 tiles, 16 b),
// 256 thr = 8 warps (4 M x 2 N), warp tile M32 x N32, NP=64 points/CTA.
// SMEM 107KB -> 2 CTAs/SM: phase latency of one CTA overlaps the other's GEMM.
// W2 planes stream into the A region mid-kernel (behind the post-GEMM1 sync).
// ---------------------------------------------------------------------------
extern __shared__ char smem[];

__global__ void __launch_bounds__(256, 2) k_local(
    int blk, int last,
    const float* __restrict__ l1b, const float* __restrict__ l2b,
    const float* __restrict__ mask,
    const float* __restrict__ outw, const float* __restrict__ outb,
    float* __restrict__ dout)
{
    char* sm = smem;
    u32 sb = s2u(sm);
    int tile = blockIdx.x, b = blockIdx.y, tid = threadIdx.x;
    int wid = tid >> 5, lane = tid & 31;
    int p0 = tile * NP;
    int mw = wid & 3, nh = wid >> 2;
    int m_base = mw * 32, n_base = nh * 32;

    // ---- prologue: W1 planes -> A region (pure int4 copies) ----
    {
        const int4* src = (const int4*)(g_wsp + (size_t)blk * 4 * TILE_B);
        int4* d1 = (int4*)(sm + O_AH);
        const int n16 = 2 * TILE_B / 16;     // 4352
        for (int idx = tid; idx < n16; idx += 256) d1[idx] = src[idx];
    }
    // xl -> B region (load fp32, split)
    const float* xbase = g_xl + (size_t)b * HH * NN + p0;
    for (int idx = tid; idx < HH * NP; idx += 256) {
        int k = idx >> 6, n = idx & 63;
        __nv_bfloat16 h, l; bsplit(xbase[(size_t)k * NN + n], h, l);
        u32 o = (u32)n * SAB + (u32)k * 2u;
        *(__nv_bfloat16*)(sm + O_BH + o) = h;
        *(__nv_bfloat16*)(sm + O_BL + o) = l;
    }
    if (tid < HH) {
        *(float*)(sm + O_B1V + tid * 4) = l1b[blk * HH + tid] + g_hb[b * HH + tid];
        *(float*)(sm + O_B2V + tid * 4) = l2b[blk * HH + tid];
    }
    if (tid < NP) *(float*)(sm + O_MK + tid * 4) = mask[(size_t)b * NN + p0 + tid];
    if (last) {
        for (int idx = tid; idx < 3 * HH; idx += 256) *(float*)(sm + O_OW + idx * 4) = outw[idx];
        if (tid < 3) *(float*)(sm + O_OB + tid * 4) = outb[tid];
    }
    __syncthreads();

    // ---- stage 1 GEMM: D1 = W1x @ xl^T ----
    float acc[32];
    #pragma unroll
    for (int i = 0; i < 32; ++i) acc[i] = 0.f;
    gemm32(sb + O_AH, sb + O_AL, sb + O_BH, sb + O_BL, lane, m_base, n_base, acc);
    __syncthreads();   // all warps done reading W1 + cat

    // ---- epilogue 1: h = lrelu(D1 + b1 + hb) -> split back into B region;
    //      concurrently stream W2 planes into the A region ----
    int r0 = lane >> 2;
    {
        const int4* src2 = (const int4*)(g_wsp + (size_t)blk * 4 * TILE_B + 2 * (size_t)TILE_B);
        int4* d2 = (int4*)(sm + O_AH);
        const int n16 = 2 * TILE_B / 16;
        for (int idx = tid; idx < n16; idx += 256) d2[idx] = src2[idx];
    }
    #pragma unroll
    for (int mi = 0; mi < 2; ++mi) {
        int rr = m_base + mi * 16 + r0;
        float b1r  = *(const float*)(sm + O_B1V + rr * 4);
        float b1r8 = *(const float*)(sm + O_B1V + (rr + 8) * 4);
        #pragma unroll
        for (int nq = 0; nq < 4; ++nq) {
            int ix = (mi * 4 + nq) * 4;
            int n0 = n_base + nq * 8 + 2 * (lane & 3);
            float v00 = lrelu(acc[ix + 0] + b1r);
            float v01 = lrelu(acc[ix + 1] + b1r);
            float v10 = lrelu(acc[ix + 2] + b1r8);
            float v11 = lrelu(acc[ix + 3] + b1r8);
            __nv_bfloat16 h, l;
            u32 o00 = (u32)n0 * SAB + (u32)rr * 2u;
            u32 o01 = o00 + SAB;
            bsplit(v00, h, l);
            *(__nv_bfloat16*)(sm + O_BH + o00) = h; *(__nv_bfloat16*)(sm + O_BL + o00) = l;
            bsplit(v01, h, l);
            *(__nv_bfloat16*)(sm + O_BH + o01) = h; *(__nv_bfloat16*)(sm + O_BL + o01) = l;
            u32 o10 = o00 + 16u, o11 = o01 + 16u;  // row rr+8
            bsplit(v10, h, l);
            *(__nv_bfloat16*)(sm + O_BH + o10) = h; *(__nv_bfloat16*)(sm + O_BL + o10) = l;
            bsplit(v11, h, l);
            *(__nv_bfloat16*)(sm + O_BH + o11) = h; *(__nv_bfloat16*)(sm + O_BL + o11) = l;
        }
    }
    __syncthreads();

    // ---- stage 2 GEMM: D2 = W2 @ h^T (same smem addresses) ----
    #pragma unroll
    for (int i = 0; i < 32; ++i) acc[i] = 0.f;
    gemm32(sb + O_AH, sb + O_AL, sb + O_BH, sb + O_BL, lane, m_base, n_base, acc);

    // ---- epilogue 2: xl_new = lrelu(D2 + b2 + xl) * mask ----
    if (!last) {
        #pragma unroll
        for (int mi = 0; mi < 2; ++mi) {
            int rr = m_base + mi * 16 + r0;
            float b2r  = *(const float*)(sm + O_B2V + rr * 4);
            float b2r8 = *(const float*)(sm + O_B2V + (rr + 8) * 4);
            float sumA = 0.f, sumB = 0.f;
            #pragma unroll
            for (int nq = 0; nq < 4; ++nq) {
                int ix = (mi * 4 + nq) * 4;
                int n0 = n_base + nq * 8 + 2 * (lane & 3);
                float mk0 = *(const float*)(sm + O_MK + n0 * 4);
                float mk1 = *(const float*)(sm + O_MK + (n0 + 1) * 4);
                float* gr  = g_xl + ((size_t)(b * HH + rr)) * NN + p0 + n0;
                float* gr8 = g_xl + ((size_t)(b * HH + rr + 8)) * NN + p0 + n0;
                float2 ra = *(const float2*)gr;
                float2 rb = *(const float2*)gr8;
                float v0 = lrelu(acc[ix + 0] + b2r + ra.x) * mk0;
                float v1 = lrelu(acc[ix + 1] + b2r + ra.y) * mk1;
                float v2 = lrelu(acc[ix + 2] + b2r8 + rb.x) * mk0;
                float v3 = lrelu(acc[ix + 3] + b2r8 + rb.y) * mk1;
                *(float2*)gr  = make_float2(v0, v1);
                *(float2*)gr8 = make_float2(v2, v3);
                sumA += v0 + v1; sumB += v2 + v3;
            }
            #pragma unroll
            for (int o = 1; o <= 2; o <<= 1) {
                sumA += __shfl_xor_sync(0xffffffffu, sumA, o);
                sumB += __shfl_xor_sync(0xffffffffu, sumB, o);
            }
            if ((lane & 3) == 0) {
                int pc = b * NPART + tile * 2 + nh;
                g_part[pc * HH + rr] = sumA;
                g_part[pc * HH + rr + 8] = sumB;
            }
        }
    } else {
        __syncthreads();   // all warps done with B/A regions before staging overwrite
        #pragma unroll
        for (int mi = 0; mi < 2; ++mi) {
            int rr = m_base + mi * 16 + r0;
            float b2r  = *(const float*)(sm + O_B2V + rr * 4);
            float b2r8 = *(const float*)(sm + O_B2V + (rr + 8) * 4);
            #pragma unroll
            for (int nq = 0; nq < 4; ++nq) {
                int ix = (mi * 4 + nq) * 4;
                int n0 = n_base + nq * 8 + 2 * (lane & 3);
                float mk0 = *(const float*)(sm + O_MK + n0 * 4);
                float mk1 = *(const float*)(sm + O_MK + (n0 + 1) * 4);
                const float* gr  = g_xl + ((size_t)(b * HH + rr)) * NN + p0 + n0;
                const float* gr8 = g_xl + ((size_t)(b * HH + rr + 8)) * NN + p0 + n0;
                float2 ra = *(const float2*)gr;
                float2 rb = *(const float2*)gr8;
                float v0 = lrelu(acc[ix + 0] + b2r + ra.x) * mk0;
                float v1 = lrelu(acc[ix + 1] + b2r + ra.y) * mk1;
                float v2 = lrelu(acc[ix + 2] + b2r8 + rb.x) * mk0;
                float v3 = lrelu(acc[ix + 3] + b2r8 + rb.y) * mk1;
                *(float*)(sm + O_STG + ((u32)n0 * 132 + rr) * 4)           = v0;
                *(float*)(sm + O_STG + ((u32)(n0 + 1) * 132 + rr) * 4)     = v1;
                *(float*)(sm + O_STG + ((u32)n0 * 132 + rr + 8) * 4)       = v2;
                *(float*)(sm + O_STG + ((u32)(n0 + 1) * 132 + rr + 8) * 4) = v3;
            }
        }
        __syncthreads();
        if (tid < NP) {
            int p = tid;
            float mk = *(const float*)(sm + O_MK + p * 4);
            float s0 = *(const float*)(sm + O_OB + 0);
            float s1 = *(const float*)(sm + O_OB + 4);
            float s2 = *(const float*)(sm + O_OB + 8);
            const float* row = (const float*)(sm + O_STG) + (u32)p * 132;
            for (int m = 0; m < HH; ++m) {
                float v = row[m];
                s0 = fmaf(v, *(const float*)(sm + O_OW + m * 4), s0);
                s1 = fmaf(v, *(const float*)(sm + O_OW + (HH + m) * 4), s1);
                s2 = fmaf(v, *(const float*)(sm + O_OW + (2 * HH + m) * 4), s2);
            }
            float* o = dout + ((size_t)b * NN + p0 + p) * 3;
            o[0] = mk * s0; o[1] = mk * s1; o[2] = mk * s2;
        }
    }
}

// ---------------------------------------------------------------------------
extern "C" void kernel_launch(void* const* d_in, const int* in_sizes, int n_in,
                              void* d_out, int out_size)
{
    const float* x_local = (const float*)d_in[0];
    const float* context = (const float*)d_in[1];
    const float* mask    = (const float*)d_in[2];
    const float* proj_lw = (const float*)d_in[3];
    const float* proj_lb = (const float*)d_in[4];
    const float* pg0w    = (const float*)d_in[5];
    const float* pg0b    = (const float*)d_in[6];
    const float* pg1w    = (const float*)d_in[7];
    const float* pg1b    = (const float*)d_in[8];
    const float* pg2w    = (const float*)d_in[9];
    const float* pg2b    = (const float*)d_in[10];
    const float* g1w     = (const float*)d_in[11];
    const float* g1b     = (const float*)d_in[12];
    const float* g2w     = (const float*)d_in[13];
    const float* g2b     = (const float*)d_in[14];
    const float* l1w     = (const float*)d_in[15];
    const float* l1b     = (const float*)d_in[16];
    const float* l2w     = (const float*)d_in[17];
    const float* l2b     = (const float*)d_in[18];
    const float* outw    = (const float*)d_in[19];
    const float* outb    = (const float*)d_in[20];
    float* out = (float*)d_out;

    cudaFuncSetAttribute(k_local, cudaFuncAttributeMaxDynamicSharedMemorySize, SMEM_SZ);

    k_prep<<<dim3(NBLK, 2), 128>>>(l1w, l2w);
    k_proj<<<dim3(16, NT0), 256>>>(x_local, mask, proj_lw, proj_lb);
    for (int blk = 0; blk < NBLK; ++blk) {
        k_global<<<16, 1024>>>(blk == 0 ? 0 : 1, blk, context,
                               pg0w, pg0b, pg1w, pg1b, pg2w, pg2b,
                               g1w, g1b, g2w, g2b, l1w);
        k_local<<<dim3(NTL, 16), 256, SMEM_SZ>>>(
            blk, blk == NBLK - 1 ? 1 : 0,
            l1b, l2b, mask, outw, outb, out);
    }
}